// round 15
// baseline (speedup 1.0000x reference)
#include <cuda_runtime.h>
#include <cuda_fp16.h>
#include <cuda_bf16.h>
#include <cstdint>

#define BB   8
#define CC   128
#define WHQ  2304
#define NN   8192

#define TQ   64
#define TN   64
#define NT   (NN/TN)
#define STRH 136     // universal b16 tile stride (halves): 272B rows, ldmatrix conflict-free

// Scratch (device globals: allocation-free rule)
__device__ __half        g_pk  [BB*NN*CC];   // [b, n, c] fp16
__device__ __nv_bfloat16 g_pv  [BB*NN*CC];   // [b, n, c] bf16
__device__ __half        g_pq  [BB*WHQ*CC];  // fp16
__device__ __half        g_geo [BB*WHQ*CC];  // fp16

__device__ __forceinline__ void mma_f16(float c[4], const uint32_t a[4], uint32_t b0, uint32_t b1) {
    asm volatile(
        "mma.sync.aligned.m16n8k16.row.col.f32.f16.f16.f32 "
        "{%0,%1,%2,%3}, {%4,%5,%6,%7}, {%8,%9}, {%0,%1,%2,%3};"
        : "+f"(c[0]), "+f"(c[1]), "+f"(c[2]), "+f"(c[3])
        : "r"(a[0]), "r"(a[1]), "r"(a[2]), "r"(a[3]), "r"(b0), "r"(b1));
}

__device__ __forceinline__ void mma_bf16(float c[4], const uint32_t a[4], uint32_t b0, uint32_t b1) {
    asm volatile(
        "mma.sync.aligned.m16n8k16.row.col.f32.bf16.bf16.f32 "
        "{%0,%1,%2,%3}, {%4,%5,%6,%7}, {%8,%9}, {%0,%1,%2,%3};"
        : "+f"(c[0]), "+f"(c[1]), "+f"(c[2]), "+f"(c[3])
        : "r"(a[0]), "r"(a[1]), "r"(a[2]), "r"(a[3]), "r"(b0), "r"(b1));
}

__device__ __forceinline__ uint32_t pack_bf16(float hi, float lo) {
    uint32_t r;
    asm("cvt.rn.bf16x2.f32 %0, %1, %2;" : "=r"(r) : "f"(hi), "f"(lo));
    return r;
}

#define LDMX4(r0, r1, r2, r3, addr) \
    asm volatile("ldmatrix.sync.aligned.m8n8.x4.shared.b16 {%0,%1,%2,%3}, [%4];" \
        : "=r"(r0), "=r"(r1), "=r"(r2), "=r"(r3) : "r"(addr))
#define LDMX4T(r0, r1, r2, r3, addr) \
    asm volatile("ldmatrix.sync.aligned.m8n8.x4.trans.shared.b16 {%0,%1,%2,%3}, [%4];" \
        : "=r"(r0), "=r"(r1), "=r"(r2), "=r"(r3) : "r"(addr))

#define CP_ASYNC16(dst_u32, src_ptr) \
    asm volatile("cp.async.cg.shared.global [%0], [%1], 16;" :: "r"(dst_u32), "l"(src_ptr))
#define CP_COMMIT() asm volatile("cp.async.commit_group;")
#define CP_WAIT0()  asm volatile("cp.async.wait_group 0;" ::: "memory")

// ---------------------------------------------------------------------------
// K1: tensor-core KV projection. 128 n-rows per CTA, occupancy 2. (unchanged)
// ---------------------------------------------------------------------------
#define KV_SA 0
#define KV_SW 34816
#define KV_SMEM (34816 + 69632)

__global__ void __launch_bounds__(256, 2) kv_proj_kernel(
    const float* __restrict__ feat1,
    const float* __restrict__ Wk, const float* __restrict__ bk,
    const float* __restrict__ Wv, const float* __restrict__ bv)
{
    extern __shared__ __align__(128) char smc[];
    __half* s_a = reinterpret_cast<__half*>(smc + KV_SA);
    __half* s_w = reinterpret_cast<__half*>(smc + KV_SW);
    const uint32_t smem_u32 = (uint32_t)__cvta_generic_to_shared(smc);

    const int b  = blockIdx.y;
    const int n0 = blockIdx.x * 128;
    const int tid = threadIdx.x;
    const int lane = tid & 31;
    const int wid  = tid >> 5;
    const int wm   = wid & 3;
    const int wn   = wid >> 2;
    const int l4   = lane & 3;
    const int ld   = lane >> 2;
    const int li   = lane & 7, lg = lane >> 3;

    #pragma unroll
    for (int i = tid; i < 128*CC; i += 256) {
        int c = i >> 7, nl = i & 127;
        s_a[nl*STRH + c] = __float2half_rn(feat1[(size_t)(b*CC + c)*NN + n0 + nl]);
    }
    #pragma unroll
    for (int i = tid; i < 2*128*CC; i += 256) {
        int w = i >> 14, rem = i & 16383;
        int c = rem >> 7, j = rem & 127;
        const float* W = w ? Wv : Wk;
        s_w[(w*128 + j)*STRH + c] = __float2half_rn(W[c*CC + j]);
    }
    __syncthreads();

    const uint32_t a_base = smem_u32 + KV_SA;
    const uint32_t b_base = smem_u32 + KV_SW +
        (uint32_t)(((lg>>1)*8 + li)*(STRH*2) + (lg&1)*16);

    #pragma unroll
    for (int mb = 0; mb < 2; mb++) {
        const uint32_t a_off = a_base +
            (uint32_t)((32*wm + 16*mb + (lg&1)*8 + li)*(STRH*2) + (lg>>1)*16);
        uint32_t a[8][4];
        #pragma unroll
        for (int kc = 0; kc < 8; kc++)
            LDMX4(a[kc][0], a[kc][1], a[kc][2], a[kc][3], a_off + kc*32);

        float acc[16][4];
        #pragma unroll
        for (int nt2 = 0; nt2 < 8; nt2++) {
            const float* bias = (nt2 < 4) ? bk : bv;
            const int c1 = 64*wn + 16*(nt2 & 3) + 2*l4;
            acc[2*nt2][0] = bias[c1];     acc[2*nt2][1] = bias[c1+1];
            acc[2*nt2][2] = bias[c1];     acc[2*nt2][3] = bias[c1+1];
            acc[2*nt2+1][0] = bias[c1+8]; acc[2*nt2+1][1] = bias[c1+9];
            acc[2*nt2+1][2] = bias[c1+8]; acc[2*nt2+1][3] = bias[c1+9];
        }

        #pragma unroll
        for (int kc = 0; kc < 8; kc++) {
            #pragma unroll
            for (int nt2 = 0; nt2 < 8; nt2++) {
                const int row_base = 128*(nt2 >> 2) + 64*wn + 16*(nt2 & 3);
                uint32_t b0, b1, b2, b3;
                LDMX4(b0, b1, b2, b3, b_base + (uint32_t)(row_base*(STRH*2)) + kc*32);
                mma_f16(acc[2*nt2],   a[kc], b0, b1);
                mma_f16(acc[2*nt2+1], a[kc], b2, b3);
            }
        }

        const int nr0 = n0 + 32*wm + 16*mb + ld;
        #pragma unroll
        for (int nt2 = 0; nt2 < 8; nt2++) {
            const int c1 = 64*wn + 16*(nt2 & 3) + 2*l4;
            if (nt2 < 4) {
                *reinterpret_cast<__half2*>(&g_pk[(size_t)(b*NN + nr0)*CC + c1]) =
                    __floats2half2_rn(acc[2*nt2][0], acc[2*nt2][1]);
                *reinterpret_cast<__half2*>(&g_pk[(size_t)(b*NN + nr0 + 8)*CC + c1]) =
                    __floats2half2_rn(acc[2*nt2][2], acc[2*nt2][3]);
                *reinterpret_cast<__half2*>(&g_pk[(size_t)(b*NN + nr0)*CC + c1 + 8]) =
                    __floats2half2_rn(acc[2*nt2+1][0], acc[2*nt2+1][1]);
                *reinterpret_cast<__half2*>(&g_pk[(size_t)(b*NN + nr0 + 8)*CC + c1 + 8]) =
                    __floats2half2_rn(acc[2*nt2+1][2], acc[2*nt2+1][3]);
            } else {
                *reinterpret_cast<uint32_t*>(&g_pv[(size_t)(b*NN + nr0)*CC + c1]) =
                    pack_bf16(acc[2*nt2][1], acc[2*nt2][0]);
                *reinterpret_cast<uint32_t*>(&g_pv[(size_t)(b*NN + nr0 + 8)*CC + c1]) =
                    pack_bf16(acc[2*nt2][3], acc[2*nt2][2]);
                *reinterpret_cast<uint32_t*>(&g_pv[(size_t)(b*NN + nr0)*CC + c1 + 8]) =
                    pack_bf16(acc[2*nt2+1][1], acc[2*nt2+1][0]);
                *reinterpret_cast<uint32_t*>(&g_pv[(size_t)(b*NN + nr0 + 8)*CC + c1 + 8]) =
                    pack_bf16(acc[2*nt2+1][3], acc[2*nt2+1][2]);
            }
        }
        if (mb == 0) __syncthreads();
    }
}

// ---------------------------------------------------------------------------
// K2: tensor-core Q/geo projection + gate. (unchanged from R14)
// ---------------------------------------------------------------------------
#define QG_SQ  0
#define QG_SG  34816
#define QG_SW  69632
#define QG_RED 139264
#define QG_SMEM (QG_RED + 1024)

__global__ void __launch_bounds__(256, 1) q_geo_kernel(
    const float* __restrict__ feat0, const float* __restrict__ geo_embed,
    const float* __restrict__ Wq, const float* __restrict__ bq,
    const float* __restrict__ Wg, const float* __restrict__ bg,
    const float* __restrict__ Wgate, const float* __restrict__ bgate)
{
    extern __shared__ __align__(128) char smc[];
    __half* s_q = reinterpret_cast<__half*>(smc + QG_SQ);
    __half* s_g = reinterpret_cast<__half*>(smc + QG_SG);
    __half* s_w = reinterpret_cast<__half*>(smc + QG_SW);
    float*  s_red = reinterpret_cast<float*>(smc + QG_RED);
    const uint32_t smem_u32 = (uint32_t)__cvta_generic_to_shared(smc);

    const int b  = blockIdx.y;
    const int q0 = blockIdx.x * 128;
    const int tid = threadIdx.x;
    const int lane = tid & 31;
    const int wid  = tid >> 5;
    const int wm   = wid & 3;
    const int wn   = wid >> 2;
    const int l4   = lane & 3;
    const int ld   = lane >> 2;
    const int li   = lane & 7, lg = lane >> 3;

    #pragma unroll
    for (int i = tid; i < 128*CC; i += 256) {
        int c = i >> 7, ql = i & 127;
        s_q[ql*STRH + c] = __float2half_rn(feat0[(size_t)(b*CC + c)*WHQ + q0 + ql]);
    }
    #pragma unroll
    for (int i = tid; i < 128*CC; i += 256) {
        int ql = i >> 7, c = i & 127;
        s_g[ql*STRH + c] = __float2half_rn(geo_embed[(size_t)(b*WHQ + q0 + ql)*CC + c]);
    }
    #pragma unroll
    for (int i = tid; i < 2*128*CC; i += 256) {
        int w = i >> 14, rem = i & 16383;
        int c = rem >> 7, j = rem & 127;
        const float* W = w ? Wg : Wq;
        s_w[(w*128 + j)*STRH + c] = __float2half_rn(W[c*CC + j]);
    }
    __syncthreads();

    const uint32_t b_base = smem_u32 + QG_SW +
        (uint32_t)(((lg>>1)*8 + li)*(STRH*2) + (lg&1)*16);
    const float gbias = bgate[0];

    #pragma unroll
    for (int mb = 0; mb < 2; mb++) {
        const uint32_t frag_off =
            (uint32_t)((32*wm + 16*mb + (lg&1)*8 + li)*(STRH*2) + (lg>>1)*16);
        uint32_t aq[8][4], ag[8][4];
        #pragma unroll
        for (int kc = 0; kc < 8; kc++) {
            LDMX4(aq[kc][0], aq[kc][1], aq[kc][2], aq[kc][3], smem_u32 + QG_SQ + frag_off + kc*32);
            LDMX4(ag[kc][0], ag[kc][1], ag[kc][2], ag[kc][3], smem_u32 + QG_SG + frag_off + kc*32);
        }

        float acc[16][4];
        #pragma unroll
        for (int nt2 = 0; nt2 < 8; nt2++) {
            const float* bias = (nt2 < 4) ? bq : bg;
            const int c1 = 64*wn + 16*(nt2 & 3) + 2*l4;
            acc[2*nt2][0] = bias[c1];     acc[2*nt2][1] = bias[c1+1];
            acc[2*nt2][2] = bias[c1];     acc[2*nt2][3] = bias[c1+1];
            acc[2*nt2+1][0] = bias[c1+8]; acc[2*nt2+1][1] = bias[c1+9];
            acc[2*nt2+1][2] = bias[c1+8]; acc[2*nt2+1][3] = bias[c1+9];
        }

        #pragma unroll
        for (int kc = 0; kc < 8; kc++) {
            #pragma unroll
            for (int nt2 = 0; nt2 < 8; nt2++) {
                const int row_base = 128*(nt2 >> 2) + 64*wn + 16*(nt2 & 3);
                uint32_t b0, b1, b2, b3;
                LDMX4(b0, b1, b2, b3, b_base + (uint32_t)(row_base*(STRH*2)) + kc*32);
                const uint32_t* A = (nt2 < 4) ? aq[kc] : ag[kc];
                mma_f16(acc[2*nt2],   A, b0, b1);
                mma_f16(acc[2*nt2+1], A, b2, b3);
            }
        }

        float p0 = 0.f, p1 = 0.f;
        #pragma unroll
        for (int nt2 = 0; nt2 < 4; nt2++) {
            const int c1 = 64*wn + 16*nt2 + 2*l4;
            const float wq0 = Wgate[c1], wq1 = Wgate[c1+1], wq8 = Wgate[c1+8], wq9 = Wgate[c1+9];
            const float wg0 = Wgate[CC+c1], wg1 = Wgate[CC+c1+1], wg8 = Wgate[CC+c1+8], wg9 = Wgate[CC+c1+9];
            p0 += acc[2*nt2][0]*wq0 + acc[2*nt2][1]*wq1 + acc[2*nt2+1][0]*wq8 + acc[2*nt2+1][1]*wq9
                + acc[8+2*nt2][0]*wg0 + acc[8+2*nt2][1]*wg1 + acc[9+2*nt2][0]*wg8 + acc[9+2*nt2][1]*wg9;
            p1 += acc[2*nt2][2]*wq0 + acc[2*nt2][3]*wq1 + acc[2*nt2+1][2]*wq8 + acc[2*nt2+1][3]*wq9
                + acc[8+2*nt2][2]*wg0 + acc[8+2*nt2][3]*wg1 + acc[9+2*nt2][2]*wg8 + acc[9+2*nt2][3]*wg9;
        }
        p0 += __shfl_xor_sync(0xffffffffu, p0, 1);
        p0 += __shfl_xor_sync(0xffffffffu, p0, 2);
        p1 += __shfl_xor_sync(0xffffffffu, p1, 1);
        p1 += __shfl_xor_sync(0xffffffffu, p1, 2);
        const int lr0 = 32*wm + 16*mb + ld;
        if (l4 == 0) { s_red[wn*128 + lr0] = p0; s_red[wn*128 + lr0 + 8] = p1; }
        __syncthreads();

        const float gate0 = 1.f / (1.f + __expf(-(s_red[lr0]     + s_red[128 + lr0]     + gbias)));
        const float gate1 = 1.f / (1.f + __expf(-(s_red[lr0 + 8] + s_red[128 + lr0 + 8] + gbias)));

        const size_t row0 = (size_t)(b*WHQ + q0 + lr0)*CC;
        const size_t row1 = (size_t)(b*WHQ + q0 + lr0 + 8)*CC;
        #pragma unroll
        for (int nt2 = 0; nt2 < 4; nt2++) {
            const int c1 = 64*wn + 16*nt2 + 2*l4;
            *reinterpret_cast<__half2*>(&g_pq[row0 + c1]) =
                __floats2half2_rn(acc[2*nt2][0] + gate0*acc[8+2*nt2][0],
                                  acc[2*nt2][1] + gate0*acc[8+2*nt2][1]);
            *reinterpret_cast<__half2*>(&g_pq[row1 + c1]) =
                __floats2half2_rn(acc[2*nt2][2] + gate1*acc[8+2*nt2][2],
                                  acc[2*nt2][3] + gate1*acc[8+2*nt2][3]);
            *reinterpret_cast<__half2*>(&g_pq[row0 + c1 + 8]) =
                __floats2half2_rn(acc[2*nt2+1][0] + gate0*acc[9+2*nt2][0],
                                  acc[2*nt2+1][1] + gate0*acc[9+2*nt2][1]);
            *reinterpret_cast<__half2*>(&g_pq[row1 + c1 + 8]) =
                __floats2half2_rn(acc[2*nt2+1][2] + gate1*acc[9+2*nt2][2],
                                  acc[2*nt2+1][3] + gate1*acc[9+2*nt2][3]);

            *reinterpret_cast<__half2*>(&g_geo[row0 + c1]) =
                __floats2half2_rn(acc[8+2*nt2][0], acc[8+2*nt2][1]);
            *reinterpret_cast<__half2*>(&g_geo[row1 + c1]) =
                __floats2half2_rn(acc[8+2*nt2][2], acc[8+2*nt2][3]);
            *reinterpret_cast<__half2*>(&g_geo[row0 + c1 + 8]) =
                __floats2half2_rn(acc[9+2*nt2][0], acc[9+2*nt2][1]);
            *reinterpret_cast<__half2*>(&g_geo[row1 + c1 + 8]) =
                __floats2half2_rn(acc[9+2*nt2][2], acc[9+2*nt2][3]);
        }
        __syncthreads();
    }
}

// ---------------------------------------------------------------------------
// K3: flash attention + FUSED out projection & final epilogue.
//     Mainloop unchanged; epilogue: merge O -> fp16 smem tile, stage Wo^T into
//     retired K buffers, O@Wo^T GEMM, sigmoid/residual, transposed store.
// ---------------------------------------------------------------------------
#define SM_QB  0
#define SM_K0B (TQ*STRH*2)                  // 17408
#define SM_K1B (2*TQ*STRH*2)                // 34816
#define SM_V0B (3*TQ*STRH*2)                // 52224
#define SM_V1B (4*TQ*STRH*2)                // 69632
#define SM_MXB (5*TQ*STRH*2)                // 87040: 128 floats
#define SM_LWB (SM_MXB + 512)               // 128 floats
#define ATTN_SMEM_BYTES (SM_LWB + 512)      // 88064 -> 2 CTAs/SM
#define SOSTR 134                            // fp32 out-tile stride (even -> 8B aligned)

__global__ void __launch_bounds__(256, 2) attn_kernel(
    const float* __restrict__ Wo, const float* __restrict__ bo,
    const float* __restrict__ feat0, float* __restrict__ out)
{
    extern __shared__ __align__(128) char smc[];
    float* smf = reinterpret_cast<float*>(smc);
    const uint32_t smem_u32 = (uint32_t)__cvta_generic_to_shared(smc);

    const int b   = blockIdx.y;
    const int q0  = blockIdx.x * TQ;
    const int tid = threadIdx.x;
    const int lane = tid & 31;
    const int wid  = tid >> 5;
    const int wm   = wid & 3;
    const int wn   = wid >> 2;
    const int l4   = lane & 3;
    const int ld   = lane >> 2;
    const int r0   = 16*wm + ld;

    float* s_mx = smf + SM_MXB/4;
    float* s_lw = smf + SM_LWB/4;

    const __half* gq = g_pq + (size_t)(b*WHQ + q0)*CC;
    const __half* gk = g_pk + (size_t)b*NN*CC;
    const __nv_bfloat16* gv = g_pv + (size_t)b*NN*CC;

    const int li = lane & 7, lg = lane >> 3;
    const uint32_t q_off = smem_u32 + SM_QB +
        (uint32_t)((16*wm + (lg&1)*8 + li)*(STRH*2) + (lg>>1)*16);
    const uint32_t k_off = (uint32_t)((32*wn + (lg>>1)*8 + li)*(STRH*2) + (lg&1)*16);
    const uint32_t v_off = (uint32_t)((32*wn + (lg&1)*8 + li)*(STRH*2) + ((lg>>1)*8)*2);

    #pragma unroll
    for (int j = 0; j < 4; j++) {
        int idx = j*256 + tid;
        int n = idx >> 4, ck = idx & 15;
        CP_ASYNC16(smem_u32 + SM_QB + (uint32_t)(n*(STRH*2) + ck*16),
                   gq + (size_t)n*CC + ck*8);
    }
    CP_COMMIT();

    auto load_tile = [&](int t, int buf) {
        const uint32_t kb = smem_u32 + (buf ? SM_K1B : SM_K0B);
        const uint32_t vb = smem_u32 + (buf ? SM_V1B : SM_V0B);
        const __half* ksrc = gk + (size_t)t*TN*CC;
        const __nv_bfloat16* vsrc = gv + (size_t)t*TN*CC;
        #pragma unroll
        for (int j = 0; j < 4; j++) {
            int idx = j*256 + tid;
            int n = idx >> 4, ck = idx & 15;
            CP_ASYNC16(kb + (uint32_t)(n*(STRH*2) + ck*16), ksrc + (size_t)n*CC + ck*8);
            CP_ASYNC16(vb + (uint32_t)(n*(STRH*2) + ck*16), vsrc + (size_t)n*CC + ck*8);
        }
        CP_COMMIT();
    };

    load_tile(0, 0);

    float oacc[16][4];
    #pragma unroll
    for (int i = 0; i < 16; i++)
        #pragma unroll
        for (int j = 0; j < 4; j++) oacc[i][j] = 0.f;
    float l_acc0 = 0.f, l_acc1 = 0.f;
    float m0a = 0.f, m0b = 0.f;

    for (int t = 0; t < NT; ++t) {
        CP_WAIT0();
        __syncthreads();
        if (t + 1 < NT) load_tile(t+1, (t+1)&1);

        const uint32_t kb = smem_u32 + ((t & 1) ? SM_K1B : SM_K0B);
        const uint32_t vb = smem_u32 + ((t & 1) ? SM_V1B : SM_V0B);

        float sacc[4][4];
        #pragma unroll
        for (int nt = 0; nt < 4; nt++)
            #pragma unroll
            for (int j = 0; j < 4; j++) sacc[nt][j] = 0.f;

        #pragma unroll
        for (int kc = 0; kc < 8; kc++) {
            uint32_t qa[4];
            LDMX4(qa[0], qa[1], qa[2], qa[3], q_off + kc*32);
            uint32_t b0, b1, b2, b3, b4, b5, b6, b7;
            LDMX4(b0, b1, b2, b3, kb + k_off + kc*32);
            LDMX4(b4, b5, b6, b7, kb + k_off + 16*(STRH*2) + kc*32);
            mma_f16(sacc[0], qa, b0, b1);
            mma_f16(sacc[1], qa, b2, b3);
            mma_f16(sacc[2], qa, b4, b5);
            mma_f16(sacc[3], qa, b6, b7);
        }

        if (t == 0) {
            float mx0 = -1e30f, mx1 = -1e30f;
            #pragma unroll
            for (int nt = 0; nt < 4; nt++) {
                mx0 = fmaxf(mx0, fmaxf(sacc[nt][0], sacc[nt][1]));
                mx1 = fmaxf(mx1, fmaxf(sacc[nt][2], sacc[nt][3]));
            }
            mx0 = fmaxf(mx0, __shfl_xor_sync(0xffffffffu, mx0, 1));
            mx0 = fmaxf(mx0, __shfl_xor_sync(0xffffffffu, mx0, 2));
            mx1 = fmaxf(mx1, __shfl_xor_sync(0xffffffffu, mx1, 1));
            mx1 = fmaxf(mx1, __shfl_xor_sync(0xffffffffu, mx1, 2));
            if (l4 == 0) { s_mx[wn*64 + r0] = mx0; s_mx[wn*64 + r0 + 8] = mx1; }
            __syncthreads();
            m0a = fmaxf(s_mx[r0],     s_mx[64 + r0]);
            m0b = fmaxf(s_mx[r0 + 8], s_mx[64 + r0 + 8]);
        }

        uint32_t pa[2][4];
        #pragma unroll
        for (int nt = 0; nt < 4; nt++) {
            float p0 = __expf(sacc[nt][0] - m0a);
            float p1 = __expf(sacc[nt][1] - m0a);
            float p2 = __expf(sacc[nt][2] - m0b);
            float p3 = __expf(sacc[nt][3] - m0b);
            l_acc0 += p0 + p1;
            l_acc1 += p2 + p3;
            const int kc = nt >> 1, o = (nt & 1) ? 2 : 0;
            pa[kc][o + 0] = pack_bf16(p1, p0);
            pa[kc][o + 1] = pack_bf16(p3, p2);
        }

        #pragma unroll
        for (int kc = 0; kc < 2; kc++) {
            const uint32_t vk = vb + v_off + (uint32_t)(kc*16*(STRH*2));
            #pragma unroll
            for (int j = 0; j < 8; j++) {
                uint32_t v0, v1, v2, v3;
                LDMX4T(v0, v1, v2, v3, vk + j*32);
                mma_bf16(oacc[2*j],   pa[kc], v0, v1);
                mma_bf16(oacc[2*j+1], pa[kc], v2, v3);
            }
        }
    }

    // ================= fused epilogue =================
    __syncthreads();   // all warps past mainloop; smem buffers free for reuse

    // l reduction
    l_acc0 += __shfl_xor_sync(0xffffffffu, l_acc0, 1);
    l_acc0 += __shfl_xor_sync(0xffffffffu, l_acc0, 2);
    l_acc1 += __shfl_xor_sync(0xffffffffu, l_acc1, 1);
    l_acc1 += __shfl_xor_sync(0xffffffffu, l_acc1, 2);
    if (l4 == 0) { s_lw[wn*64 + r0] = l_acc0; s_lw[wn*64 + r0 + 8] = l_acc1; }

    // wn==1 exports split-K partial (fp32) into V-buffer region
    float* sM = smf + SM_V0B/4;   // 64 x 130 fp32 = 33280 <= 36864
    if (wn == 1) {
        #pragma unroll
        for (int nt = 0; nt < 16; nt++) {
            const int col = 8*nt + 2*l4;
            *reinterpret_cast<float2*>(&sM[(r0    )*130 + col]) = make_float2(oacc[nt][0], oacc[nt][1]);
            *reinterpret_cast<float2*>(&sM[(r0 + 8)*130 + col]) = make_float2(oacc[nt][2], oacc[nt][3]);
        }
    }
    __syncthreads();

    // wn==0 merges + scales + writes fp16 O tile into Q region
    __half* sOt = reinterpret_cast<__half*>(smc + SM_QB);
    if (wn == 0) {
        const float inv0 = 1.f / ((s_lw[r0]     + s_lw[64 + r0]    ) * 11.313708499f);
        const float inv1 = 1.f / ((s_lw[r0 + 8] + s_lw[64 + r0 + 8]) * 11.313708499f);
        #pragma unroll
        for (int nt = 0; nt < 16; nt++) {
            const int col = 8*nt + 2*l4;
            float2 p0 = *reinterpret_cast<const float2*>(&sM[(r0    )*130 + col]);
            float2 p1 = *reinterpret_cast<const float2*>(&sM[(r0 + 8)*130 + col]);
            *reinterpret_cast<__half2*>(&sOt[(r0    )*STRH + col]) =
                __floats2half2_rn((oacc[nt][0] + p0.x)*inv0, (oacc[nt][1] + p0.y)*inv0);
            *reinterpret_cast<__half2*>(&sOt[(r0 + 8)*STRH + col]) =
                __floats2half2_rn((oacc[nt][2] + p1.x)*inv1, (oacc[nt][3] + p1.y)*inv1);
        }
    }
    // stage Wo^T into K buffers (all threads)
    __half* s_wo = reinterpret_cast<__half*>(smc + SM_K0B);   // 128 x 136h = 34816 = K0+K1
    #pragma unroll
    for (int i = tid; i < 128*CC; i += 256) {
        int c = i >> 7, j = i & 127;
        s_wo[j*STRH + c] = __float2half_rn(Wo[c*CC + j]);
    }
    __syncthreads();

    // O @ Wo^T (all 8 warps; wn splits output cols)
    const uint32_t a_off2 = smem_u32 + SM_QB +
        (uint32_t)((16*wm + (lg&1)*8 + li)*(STRH*2) + (lg>>1)*16);
    const uint32_t b_base2 = smem_u32 + SM_K0B +
        (uint32_t)((64*wn + (lg>>1)*8 + li)*(STRH*2) + (lg&1)*16);

    float acc[8][4];
    #pragma unroll
    for (int i = 0; i < 8; i++)
        #pragma unroll
        for (int j = 0; j < 4; j++) acc[i][j] = 0.f;

    #pragma unroll
    for (int kc = 0; kc < 8; kc++) {
        uint32_t a[4];
        LDMX4(a[0], a[1], a[2], a[3], a_off2 + kc*32);
        #pragma unroll
        for (int nt2 = 0; nt2 < 4; nt2++) {
            uint32_t b0, b1, b2, b3;
            LDMX4(b0, b1, b2, b3, b_base2 + (uint32_t)(nt2*16*(STRH*2)) + kc*32);
            mma_f16(acc[2*nt2],   a, b0, b1);
            mma_f16(acc[2*nt2+1], a, b2, b3);
        }
    }

    // write result fp32 into V-buffer region (sM reads complete before this barrier)
    float* s_o = smf + SM_V0B/4;   // 64 x 134 fp32 = 34304 <= 36864
    __syncthreads();               // sM no longer needed; safe rewrite
    #pragma unroll
    for (int nt = 0; nt < 8; nt++) {
        const int col = 64*wn + 8*nt + 2*l4;
        *reinterpret_cast<float2*>(&s_o[(r0    )*SOSTR + col]) = make_float2(acc[nt][0], acc[nt][1]);
        *reinterpret_cast<float2*>(&s_o[(r0 + 8)*SOSTR + col]) = make_float2(acc[nt][2], acc[nt][3]);
    }
    __syncthreads();

    // scalar epilogue: +bo, *(1+sigmoid(geo)), +feat0, transposed store
    #pragma unroll
    for (int i = tid; i < TQ*CC; i += 256) {
        const int c = i >> 6, q = i & 63;
        const float v = s_o[q*SOSTR + c] + bo[c];
        const float g = __half2float(g_geo[(size_t)(b*WHQ + q0 + q)*CC + c]);
        const float sig = 1.f / (1.f + __expf(-g));
        const size_t oi = (size_t)(b*CC + c)*WHQ + q0 + q;
        out[oi] = v*(1.f + sig) + feat0[oi];
    }
}

// ---------------------------------------------------------------------------
extern "C" void kernel_launch(void* const* d_in, const int* in_sizes, int n_in,
                              void* d_out, int out_size)
{
    const float* feat0     = (const float*)d_in[0];
    const float* feat1     = (const float*)d_in[1];
    const float* geo_embed = (const float*)d_in[2];
    const float* Wq = (const float*)d_in[3];
    const float* bq = (const float*)d_in[4];
    const float* Wk = (const float*)d_in[5];
    const float* bk = (const float*)d_in[6];
    const float* Wv = (const float*)d_in[7];
    const float* bv = (const float*)d_in[8];
    const float* Wo = (const float*)d_in[9];
    const float* bo = (const float*)d_in[10];
    const float* Wg = (const float*)d_in[11];
    const float* bg = (const float*)d_in[12];
    const float* Wgate = (const float*)d_in[13];
    const float* bgate = (const float*)d_in[14];
    float* out = (float*)d_out;

    cudaFuncSetAttribute(attn_kernel,
                         cudaFuncAttributeMaxDynamicSharedMemorySize, ATTN_SMEM_BYTES);
    cudaFuncSetAttribute(kv_proj_kernel,
                         cudaFuncAttributeMaxDynamicSharedMemorySize, KV_SMEM);
    cudaFuncSetAttribute(q_geo_kernel,
                         cudaFuncAttributeMaxDynamicSharedMemorySize, QG_SMEM);

    kv_proj_kernel<<<dim3(NN/128, BB), 256, KV_SMEM>>>(feat1, Wk, bk, Wv, bv);
    q_geo_kernel<<<dim3(WHQ/128, BB), 256, QG_SMEM>>>(feat0, geo_embed, Wq, bq, Wg, bg, Wgate, bgate);
    attn_kernel<<<dim3(WHQ/TQ, BB), 256, ATTN_SMEM_BYTES>>>(Wo, bo, feat0, out);
}

// round 16
// speedup vs baseline: 1.0168x; 1.0168x over previous
#include <cuda_runtime.h>
#include <cuda_fp16.h>
#include <cuda_bf16.h>
#include <cstdint>

#define BB   8
#define CC   128
#define WHQ  2304
#define NN   8192

#define TQ   64
#define TN   64
#define NT   (NN/TN)
#define STRH 136     // universal b16 tile stride (halves): 272B rows, ldmatrix conflict-free

// Scratch (device globals: allocation-free rule)
__device__ __half        g_pk  [BB*NN*CC];   // [b, n, c] fp16
__device__ __nv_bfloat16 g_pv  [BB*NN*CC];   // [b, n, c] bf16
__device__ __half        g_pq  [BB*WHQ*CC];  // fp16
__device__ __half        g_geo [BB*WHQ*CC];  // fp16
__device__ __half        g_attn[BB*WHQ*CC];  // fp16

__device__ __forceinline__ void mma_f16(float c[4], const uint32_t a[4], uint32_t b0, uint32_t b1) {
    asm volatile(
        "mma.sync.aligned.m16n8k16.row.col.f32.f16.f16.f32 "
        "{%0,%1,%2,%3}, {%4,%5,%6,%7}, {%8,%9}, {%0,%1,%2,%3};"
        : "+f"(c[0]), "+f"(c[1]), "+f"(c[2]), "+f"(c[3])
        : "r"(a[0]), "r"(a[1]), "r"(a[2]), "r"(a[3]), "r"(b0), "r"(b1));
}

__device__ __forceinline__ void mma_bf16(float c[4], const uint32_t a[4], uint32_t b0, uint32_t b1) {
    asm volatile(
        "mma.sync.aligned.m16n8k16.row.col.f32.bf16.bf16.f32 "
        "{%0,%1,%2,%3}, {%4,%5,%6,%7}, {%8,%9}, {%0,%1,%2,%3};"
        : "+f"(c[0]), "+f"(c[1]), "+f"(c[2]), "+f"(c[3])
        : "r"(a[0]), "r"(a[1]), "r"(a[2]), "r"(a[3]), "r"(b0), "r"(b1));
}

__device__ __forceinline__ uint32_t pack_bf16(float hi, float lo) {
    uint32_t r;
    asm("cvt.rn.bf16x2.f32 %0, %1, %2;" : "=r"(r) : "f"(hi), "f"(lo));
    return r;
}

#define LDMX4(r0, r1, r2, r3, addr) \
    asm volatile("ldmatrix.sync.aligned.m8n8.x4.shared.b16 {%0,%1,%2,%3}, [%4];" \
        : "=r"(r0), "=r"(r1), "=r"(r2), "=r"(r3) : "r"(addr))
#define LDMX4T(r0, r1, r2, r3, addr) \
    asm volatile("ldmatrix.sync.aligned.m8n8.x4.trans.shared.b16 {%0,%1,%2,%3}, [%4];" \
        : "=r"(r0), "=r"(r1), "=r"(r2), "=r"(r3) : "r"(addr))

#define CP_ASYNC16(dst_u32, src_ptr) \
    asm volatile("cp.async.cg.shared.global [%0], [%1], 16;" :: "r"(dst_u32), "l"(src_ptr))
#define CP_COMMIT() asm volatile("cp.async.commit_group;")
#define CP_WAIT0()  asm volatile("cp.async.wait_group 0;" ::: "memory")

// ---------------------------------------------------------------------------
// K1: tensor-core KV projection. 128 n-rows per CTA, occupancy 2.
//     Weights staged ROW-MAJOR s_w[c][j] (conflict-free), B-frags via LDMX4T.
// ---------------------------------------------------------------------------
#define KV_SA 0
#define KV_SW 34816
#define KV_WT (128*STRH*2)               // bytes per weight tile (Wk / Wv)
#define KV_SMEM (34816 + 2*KV_WT)

__global__ void __launch_bounds__(256, 2) kv_proj_kernel(
    const float* __restrict__ feat1,
    const float* __restrict__ Wk, const float* __restrict__ bk,
    const float* __restrict__ Wv, const float* __restrict__ bv)
{
    extern __shared__ __align__(128) char smc[];
    __half* s_a = reinterpret_cast<__half*>(smc + KV_SA);
    __half* s_w = reinterpret_cast<__half*>(smc + KV_SW);
    const uint32_t smem_u32 = (uint32_t)__cvta_generic_to_shared(smc);

    const int b  = blockIdx.y;
    const int n0 = blockIdx.x * 128;
    const int tid = threadIdx.x;
    const int lane = tid & 31;
    const int wid  = tid >> 5;
    const int wm   = wid & 3;
    const int wn   = wid >> 2;
    const int l4   = lane & 3;
    const int ld   = lane >> 2;
    const int li   = lane & 7, lg = lane >> 3;

    #pragma unroll
    for (int i = tid; i < 128*CC; i += 256) {
        int c = i >> 7, nl = i & 127;
        s_a[nl*STRH + c] = __float2half_rn(feat1[(size_t)(b*CC + c)*NN + n0 + nl]);
    }
    // weights row-major: s_w[w][c][j] — conflict-free stores
    #pragma unroll
    for (int i = tid; i < 2*128*CC; i += 256) {
        int w = i >> 14, rem = i & 16383;
        int c = rem >> 7, j = rem & 127;
        const float* W = w ? Wv : Wk;
        s_w[(w*128 + c)*STRH + j] = __float2half_rn(W[c*CC + j]);
    }
    __syncthreads();

    const uint32_t a_base = smem_u32 + KV_SA;
    // trans B-frag lane offset: rows = c (k-dim), cols = j (n-dim)
    const uint32_t wb_off = (uint32_t)(((lg&1)*8 + li)*(STRH*2) + ((lg>>1)*8)*2);

    #pragma unroll
    for (int mb = 0; mb < 2; mb++) {
        const uint32_t a_off = a_base +
            (uint32_t)((32*wm + 16*mb + (lg&1)*8 + li)*(STRH*2) + (lg>>1)*16);
        uint32_t a[8][4];
        #pragma unroll
        for (int kc = 0; kc < 8; kc++)
            LDMX4(a[kc][0], a[kc][1], a[kc][2], a[kc][3], a_off + kc*32);

        float acc[16][4];
        #pragma unroll
        for (int nt2 = 0; nt2 < 8; nt2++) {
            const float* bias = (nt2 < 4) ? bk : bv;
            const int c1 = 64*wn + 16*(nt2 & 3) + 2*l4;
            acc[2*nt2][0] = bias[c1];     acc[2*nt2][1] = bias[c1+1];
            acc[2*nt2][2] = bias[c1];     acc[2*nt2][3] = bias[c1+1];
            acc[2*nt2+1][0] = bias[c1+8]; acc[2*nt2+1][1] = bias[c1+9];
            acc[2*nt2+1][2] = bias[c1+8]; acc[2*nt2+1][3] = bias[c1+9];
        }

        #pragma unroll
        for (int kc = 0; kc < 8; kc++) {
            #pragma unroll
            for (int nt2 = 0; nt2 < 8; nt2++) {
                const uint32_t tile = smem_u32 + KV_SW + ((nt2 >= 4) ? KV_WT : 0);
                const int col0 = 64*wn + 16*(nt2 & 3);
                uint32_t b0, b1, b2, b3;
                LDMX4T(b0, b1, b2, b3,
                       tile + wb_off + (uint32_t)(kc*16*(STRH*2) + col0*2));
                mma_f16(acc[2*nt2],   a[kc], b0, b1);
                mma_f16(acc[2*nt2+1], a[kc], b2, b3);
            }
        }

        const int nr0 = n0 + 32*wm + 16*mb + ld;
        #pragma unroll
        for (int nt2 = 0; nt2 < 8; nt2++) {
            const int c1 = 64*wn + 16*(nt2 & 3) + 2*l4;
            if (nt2 < 4) {
                *reinterpret_cast<__half2*>(&g_pk[(size_t)(b*NN + nr0)*CC + c1]) =
                    __floats2half2_rn(acc[2*nt2][0], acc[2*nt2][1]);
                *reinterpret_cast<__half2*>(&g_pk[(size_t)(b*NN + nr0 + 8)*CC + c1]) =
                    __floats2half2_rn(acc[2*nt2][2], acc[2*nt2][3]);
                *reinterpret_cast<__half2*>(&g_pk[(size_t)(b*NN + nr0)*CC + c1 + 8]) =
                    __floats2half2_rn(acc[2*nt2+1][0], acc[2*nt2+1][1]);
                *reinterpret_cast<__half2*>(&g_pk[(size_t)(b*NN + nr0 + 8)*CC + c1 + 8]) =
                    __floats2half2_rn(acc[2*nt2+1][2], acc[2*nt2+1][3]);
            } else {
                *reinterpret_cast<uint32_t*>(&g_pv[(size_t)(b*NN + nr0)*CC + c1]) =
                    pack_bf16(acc[2*nt2][1], acc[2*nt2][0]);
                *reinterpret_cast<uint32_t*>(&g_pv[(size_t)(b*NN + nr0 + 8)*CC + c1]) =
                    pack_bf16(acc[2*nt2][3], acc[2*nt2][2]);
                *reinterpret_cast<uint32_t*>(&g_pv[(size_t)(b*NN + nr0)*CC + c1 + 8]) =
                    pack_bf16(acc[2*nt2+1][1], acc[2*nt2+1][0]);
                *reinterpret_cast<uint32_t*>(&g_pv[(size_t)(b*NN + nr0 + 8)*CC + c1 + 8]) =
                    pack_bf16(acc[2*nt2+1][3], acc[2*nt2+1][2]);
            }
        }
        if (mb == 0) __syncthreads();
    }
}

// ---------------------------------------------------------------------------
// K2: tensor-core Q/geo projection + gate. Weights row-major + LDMX4T.
// ---------------------------------------------------------------------------
#define QG_SQ  0
#define QG_SG  34816
#define QG_SW  69632
#define QG_WT  (128*STRH*2)
#define QG_RED (QG_SW + 2*QG_WT)
#define QG_SMEM (QG_RED + 1024)

__global__ void __launch_bounds__(256, 1) q_geo_kernel(
    const float* __restrict__ feat0, const float* __restrict__ geo_embed,
    const float* __restrict__ Wq, const float* __restrict__ bq,
    const float* __restrict__ Wg, const float* __restrict__ bg,
    const float* __restrict__ Wgate, const float* __restrict__ bgate)
{
    extern __shared__ __align__(128) char smc[];
    __half* s_q = reinterpret_cast<__half*>(smc + QG_SQ);
    __half* s_g = reinterpret_cast<__half*>(smc + QG_SG);
    __half* s_w = reinterpret_cast<__half*>(smc + QG_SW);
    float*  s_red = reinterpret_cast<float*>(smc + QG_RED);
    const uint32_t smem_u32 = (uint32_t)__cvta_generic_to_shared(smc);

    const int b  = blockIdx.y;
    const int q0 = blockIdx.x * 128;
    const int tid = threadIdx.x;
    const int lane = tid & 31;
    const int wid  = tid >> 5;
    const int wm   = wid & 3;
    const int wn   = wid >> 2;
    const int l4   = lane & 3;
    const int ld   = lane >> 2;
    const int li   = lane & 7, lg = lane >> 3;

    #pragma unroll
    for (int i = tid; i < 128*CC; i += 256) {
        int c = i >> 7, ql = i & 127;
        s_q[ql*STRH + c] = __float2half_rn(feat0[(size_t)(b*CC + c)*WHQ + q0 + ql]);
    }
    #pragma unroll
    for (int i = tid; i < 128*CC; i += 256) {
        int ql = i >> 7, c = i & 127;
        s_g[ql*STRH + c] = __float2half_rn(geo_embed[(size_t)(b*WHQ + q0 + ql)*CC + c]);
    }
    // weights row-major: s_w[w][c][j]
    #pragma unroll
    for (int i = tid; i < 2*128*CC; i += 256) {
        int w = i >> 14, rem = i & 16383;
        int c = rem >> 7, j = rem & 127;
        const float* W = w ? Wg : Wq;
        s_w[(w*128 + c)*STRH + j] = __float2half_rn(W[c*CC + j]);
    }
    __syncthreads();

    const uint32_t wb_off = (uint32_t)(((lg&1)*8 + li)*(STRH*2) + ((lg>>1)*8)*2);
    const float gbias = bgate[0];

    #pragma unroll
    for (int mb = 0; mb < 2; mb++) {
        const uint32_t frag_off =
            (uint32_t)((32*wm + 16*mb + (lg&1)*8 + li)*(STRH*2) + (lg>>1)*16);
        uint32_t aq[8][4], ag[8][4];
        #pragma unroll
        for (int kc = 0; kc < 8; kc++) {
            LDMX4(aq[kc][0], aq[kc][1], aq[kc][2], aq[kc][3], smem_u32 + QG_SQ + frag_off + kc*32);
            LDMX4(ag[kc][0], ag[kc][1], ag[kc][2], ag[kc][3], smem_u32 + QG_SG + frag_off + kc*32);
        }

        float acc[16][4];
        #pragma unroll
        for (int nt2 = 0; nt2 < 8; nt2++) {
            const float* bias = (nt2 < 4) ? bq : bg;
            const int c1 = 64*wn + 16*(nt2 & 3) + 2*l4;
            acc[2*nt2][0] = bias[c1];     acc[2*nt2][1] = bias[c1+1];
            acc[2*nt2][2] = bias[c1];     acc[2*nt2][3] = bias[c1+1];
            acc[2*nt2+1][0] = bias[c1+8]; acc[2*nt2+1][1] = bias[c1+9];
            acc[2*nt2+1][2] = bias[c1+8]; acc[2*nt2+1][3] = bias[c1+9];
        }

        #pragma unroll
        for (int kc = 0; kc < 8; kc++) {
            #pragma unroll
            for (int nt2 = 0; nt2 < 8; nt2++) {
                const uint32_t tile = smem_u32 + QG_SW + ((nt2 >= 4) ? QG_WT : 0);
                const int col0 = 64*wn + 16*(nt2 & 3);
                uint32_t b0, b1, b2, b3;
                LDMX4T(b0, b1, b2, b3,
                       tile + wb_off + (uint32_t)(kc*16*(STRH*2) + col0*2));
                const uint32_t* A = (nt2 < 4) ? aq[kc] : ag[kc];
                mma_f16(acc[2*nt2],   A, b0, b1);
                mma_f16(acc[2*nt2+1], A, b2, b3);
            }
        }

        float p0 = 0.f, p1 = 0.f;
        #pragma unroll
        for (int nt2 = 0; nt2 < 4; nt2++) {
            const int c1 = 64*wn + 16*nt2 + 2*l4;
            const float wq0 = Wgate[c1], wq1 = Wgate[c1+1], wq8 = Wgate[c1+8], wq9 = Wgate[c1+9];
            const float wg0 = Wgate[CC+c1], wg1 = Wgate[CC+c1+1], wg8 = Wgate[CC+c1+8], wg9 = Wgate[CC+c1+9];
            p0 += acc[2*nt2][0]*wq0 + acc[2*nt2][1]*wq1 + acc[2*nt2+1][0]*wq8 + acc[2*nt2+1][1]*wq9
                + acc[8+2*nt2][0]*wg0 + acc[8+2*nt2][1]*wg1 + acc[9+2*nt2][0]*wg8 + acc[9+2*nt2][1]*wg9;
            p1 += acc[2*nt2][2]*wq0 + acc[2*nt2][3]*wq1 + acc[2*nt2+1][2]*wq8 + acc[2*nt2+1][3]*wq9
                + acc[8+2*nt2][2]*wg0 + acc[8+2*nt2][3]*wg1 + acc[9+2*nt2][2]*wg8 + acc[9+2*nt2][3]*wg9;
        }
        p0 += __shfl_xor_sync(0xffffffffu, p0, 1);
        p0 += __shfl_xor_sync(0xffffffffu, p0, 2);
        p1 += __shfl_xor_sync(0xffffffffu, p1, 1);
        p1 += __shfl_xor_sync(0xffffffffu, p1, 2);
        const int lr0 = 32*wm + 16*mb + ld;
        if (l4 == 0) { s_red[wn*128 + lr0] = p0; s_red[wn*128 + lr0 + 8] = p1; }
        __syncthreads();

        const float gate0 = 1.f / (1.f + __expf(-(s_red[lr0]     + s_red[128 + lr0]     + gbias)));
        const float gate1 = 1.f / (1.f + __expf(-(s_red[lr0 + 8] + s_red[128 + lr0 + 8] + gbias)));

        const size_t row0 = (size_t)(b*WHQ + q0 + lr0)*CC;
        const size_t row1 = (size_t)(b*WHQ + q0 + lr0 + 8)*CC;
        #pragma unroll
        for (int nt2 = 0; nt2 < 4; nt2++) {
            const int c1 = 64*wn + 16*nt2 + 2*l4;
            *reinterpret_cast<__half2*>(&g_pq[row0 + c1]) =
                __floats2half2_rn(acc[2*nt2][0] + gate0*acc[8+2*nt2][0],
                                  acc[2*nt2][1] + gate0*acc[8+2*nt2][1]);
            *reinterpret_cast<__half2*>(&g_pq[row1 + c1]) =
                __floats2half2_rn(acc[2*nt2][2] + gate1*acc[8+2*nt2][2],
                                  acc[2*nt2][3] + gate1*acc[8+2*nt2][3]);
            *reinterpret_cast<__half2*>(&g_pq[row0 + c1 + 8]) =
                __floats2half2_rn(acc[2*nt2+1][0] + gate0*acc[9+2*nt2][0],
                                  acc[2*nt2+1][1] + gate0*acc[9+2*nt2][1]);
            *reinterpret_cast<__half2*>(&g_pq[row1 + c1 + 8]) =
                __floats2half2_rn(acc[2*nt2+1][2] + gate1*acc[9+2*nt2][2],
                                  acc[2*nt2+1][3] + gate1*acc[9+2*nt2][3]);

            *reinterpret_cast<__half2*>(&g_geo[row0 + c1]) =
                __floats2half2_rn(acc[8+2*nt2][0], acc[8+2*nt2][1]);
            *reinterpret_cast<__half2*>(&g_geo[row1 + c1]) =
                __floats2half2_rn(acc[8+2*nt2][2], acc[8+2*nt2][3]);
            *reinterpret_cast<__half2*>(&g_geo[row0 + c1 + 8]) =
                __floats2half2_rn(acc[9+2*nt2][0], acc[9+2*nt2][1]);
            *reinterpret_cast<__half2*>(&g_geo[row1 + c1 + 8]) =
                __floats2half2_rn(acc[9+2*nt2][2], acc[9+2*nt2][3]);
        }
        __syncthreads();
    }
}

// ---------------------------------------------------------------------------
// K3: flash attention, occupancy 2 (R14 version, unfused)
// ---------------------------------------------------------------------------
#define SM_QB  0
#define SM_K0B (TQ*STRH*2)
#define SM_K1B (2*TQ*STRH*2)
#define SM_V0B (3*TQ*STRH*2)
#define SM_V1B (4*TQ*STRH*2)
#define SM_MXB (5*TQ*STRH*2)
#define SM_LWB (SM_MXB + 512)
#define ATTN_SMEM_BYTES (SM_LWB + 512)

__global__ void __launch_bounds__(256, 2) attn_kernel()
{
    extern __shared__ __align__(128) char smc[];
    float* smf = reinterpret_cast<float*>(smc);
    const uint32_t smem_u32 = (uint32_t)__cvta_generic_to_shared(smc);

    const int b   = blockIdx.y;
    const int q0  = blockIdx.x * TQ;
    const int tid = threadIdx.x;
    const int lane = tid & 31;
    const int wid  = tid >> 5;
    const int wm   = wid & 3;
    const int wn   = wid >> 2;
    const int l4   = lane & 3;
    const int ld   = lane >> 2;
    const int r0   = 16*wm + ld;

    float* s_mx = smf + SM_MXB/4;
    float* s_lw = smf + SM_LWB/4;

    const __half* gq = g_pq + (size_t)(b*WHQ + q0)*CC;
    const __half* gk = g_pk + (size_t)b*NN*CC;
    const __nv_bfloat16* gv = g_pv + (size_t)b*NN*CC;

    const int li = lane & 7, lg = lane >> 3;
    const uint32_t q_off = smem_u32 + SM_QB +
        (uint32_t)((16*wm + (lg&1)*8 + li)*(STRH*2) + (lg>>1)*16);
    const uint32_t k_off = (uint32_t)((32*wn + (lg>>1)*8 + li)*(STRH*2) + (lg&1)*16);
    const uint32_t v_off = (uint32_t)((32*wn + (lg&1)*8 + li)*(STRH*2) + ((lg>>1)*8)*2);

    #pragma unroll
    for (int j = 0; j < 4; j++) {
        int idx = j*256 + tid;
        int n = idx >> 4, ck = idx & 15;
        CP_ASYNC16(smem_u32 + SM_QB + (uint32_t)(n*(STRH*2) + ck*16),
                   gq + (size_t)n*CC + ck*8);
    }
    CP_COMMIT();

    auto load_tile = [&](int t, int buf) {
        const uint32_t kb = smem_u32 + (buf ? SM_K1B : SM_K0B);
        const uint32_t vb = smem_u32 + (buf ? SM_V1B : SM_V0B);
        const __half* ksrc = gk + (size_t)t*TN*CC;
        const __nv_bfloat16* vsrc = gv + (size_t)t*TN*CC;
        #pragma unroll
        for (int j = 0; j < 4; j++) {
            int idx = j*256 + tid;
            int n = idx >> 4, ck = idx & 15;
            CP_ASYNC16(kb + (uint32_t)(n*(STRH*2) + ck*16), ksrc + (size_t)n*CC + ck*8);
            CP_ASYNC16(vb + (uint32_t)(n*(STRH*2) + ck*16), vsrc + (size_t)n*CC + ck*8);
        }
        CP_COMMIT();
    };

    load_tile(0, 0);

    float oacc[16][4];
    #pragma unroll
    for (int i = 0; i < 16; i++)
        #pragma unroll
        for (int j = 0; j < 4; j++) oacc[i][j] = 0.f;
    float l_acc0 = 0.f, l_acc1 = 0.f;
    float m0a = 0.f, m0b = 0.f;

    for (int t = 0; t < NT; ++t) {
        CP_WAIT0();
        __syncthreads();
        if (t + 1 < NT) load_tile(t+1, (t+1)&1);

        const uint32_t kb = smem_u32 + ((t & 1) ? SM_K1B : SM_K0B);
        const uint32_t vb = smem_u32 + ((t & 1) ? SM_V1B : SM_V0B);

        float sacc[4][4];
        #pragma unroll
        for (int nt = 0; nt < 4; nt++)
            #pragma unroll
            for (int j = 0; j < 4; j++) sacc[nt][j] = 0.f;

        #pragma unroll
        for (int kc = 0; kc < 8; kc++) {
            uint32_t qa[4];
            LDMX4(qa[0], qa[1], qa[2], qa[3], q_off + kc*32);
            uint32_t b0, b1, b2, b3, b4, b5, b6, b7;
            LDMX4(b0, b1, b2, b3, kb + k_off + kc*32);
            LDMX4(b4, b5, b6, b7, kb + k_off + 16*(STRH*2) + kc*32);
            mma_f16(sacc[0], qa, b0, b1);
            mma_f16(sacc[1], qa, b2, b3);
            mma_f16(sacc[2], qa, b4, b5);
            mma_f16(sacc[3], qa, b6, b7);
        }

        if (t == 0) {
            float mx0 = -1e30f, mx1 = -1e30f;
            #pragma unroll
            for (int nt = 0; nt < 4; nt++) {
                mx0 = fmaxf(mx0, fmaxf(sacc[nt][0], sacc[nt][1]));
                mx1 = fmaxf(mx1, fmaxf(sacc[nt][2], sacc[nt][3]));
            }
            mx0 = fmaxf(mx0, __shfl_xor_sync(0xffffffffu, mx0, 1));
            mx0 = fmaxf(mx0, __shfl_xor_sync(0xffffffffu, mx0, 2));
            mx1 = fmaxf(mx1, __shfl_xor_sync(0xffffffffu, mx1, 1));
            mx1 = fmaxf(mx1, __shfl_xor_sync(0xffffffffu, mx1, 2));
            if (l4 == 0) { s_mx[wn*64 + r0] = mx0; s_mx[wn*64 + r0 + 8] = mx1; }
            __syncthreads();
            m0a = fmaxf(s_mx[r0],     s_mx[64 + r0]);
            m0b = fmaxf(s_mx[r0 + 8], s_mx[64 + r0 + 8]);
        }

        uint32_t pa[2][4];
        #pragma unroll
        for (int nt = 0; nt < 4; nt++) {
            float p0 = __expf(sacc[nt][0] - m0a);
            float p1 = __expf(sacc[nt][1] - m0a);
            float p2 = __expf(sacc[nt][2] - m0b);
            float p3 = __expf(sacc[nt][3] - m0b);
            l_acc0 += p0 + p1;
            l_acc1 += p2 + p3;
            const int kc = nt >> 1, o = (nt & 1) ? 2 : 0;
            pa[kc][o + 0] = pack_bf16(p1, p0);
            pa[kc][o + 1] = pack_bf16(p3, p2);
        }

        #pragma unroll
        for (int kc = 0; kc < 2; kc++) {
            const uint32_t vk = vb + v_off + (uint32_t)(kc*16*(STRH*2));
            #pragma unroll
            for (int j = 0; j < 8; j++) {
                uint32_t v0, v1, v2, v3;
                LDMX4T(v0, v1, v2, v3, vk + j*32);
                mma_bf16(oacc[2*j],   pa[kc], v0, v1);
                mma_bf16(oacc[2*j+1], pa[kc], v2, v3);
            }
        }
    }

    l_acc0 += __shfl_xor_sync(0xffffffffu, l_acc0, 1);
    l_acc0 += __shfl_xor_sync(0xffffffffu, l_acc0, 2);
    l_acc1 += __shfl_xor_sync(0xffffffffu, l_acc1, 1);
    l_acc1 += __shfl_xor_sync(0xffffffffu, l_acc1, 2);
    if (l4 == 0) { s_lw[wn*64 + r0] = l_acc0; s_lw[wn*64 + r0 + 8] = l_acc1; }

    float* sO = smf + SM_K0B/4;
    if (wn == 1) {
        #pragma unroll
        for (int nt = 0; nt < 16; nt++) {
            const int col = 8*nt + 2*l4;
            *reinterpret_cast<float2*>(&sO[(r0    )*130 + col]) = make_float2(oacc[nt][0], oacc[nt][1]);
            *reinterpret_cast<float2*>(&sO[(r0 + 8)*130 + col]) = make_float2(oacc[nt][2], oacc[nt][3]);
        }
    }
    __syncthreads();
    if (wn == 0) {
        const float inv0 = 1.f / ((s_lw[r0]     + s_lw[64 + r0]    ) * 11.313708499f);
        const float inv1 = 1.f / ((s_lw[r0 + 8] + s_lw[64 + r0 + 8]) * 11.313708499f);
        #pragma unroll
        for (int nt = 0; nt < 16; nt++) {
            const int col = 8*nt + 2*l4;
            float2 p0 = *reinterpret_cast<const float2*>(&sO[(r0    )*130 + col]);
            float2 p1 = *reinterpret_cast<const float2*>(&sO[(r0 + 8)*130 + col]);
            *reinterpret_cast<__half2*>(&g_attn[(size_t)(b*WHQ + q0 + r0)*CC + col]) =
                __floats2half2_rn((oacc[nt][0] + p0.x)*inv0, (oacc[nt][1] + p0.y)*inv0);
            *reinterpret_cast<__half2*>(&g_attn[(size_t)(b*WHQ + q0 + r0 + 8)*CC + col]) =
                __floats2half2_rn((oacc[nt][2] + p1.x)*inv1, (oacc[nt][3] + p1.y)*inv1);
        }
    }
}

// ---------------------------------------------------------------------------
// K4: tensor-core out projection, 64 q-rows per CTA, occupancy 2.
//     Wo staged row-major + LDMX4T B-frags.
// ---------------------------------------------------------------------------
#define OUT_SA 0
#define OUT_SW 17408
#define OUT_SO (17408 + 34816)
#define SOSTR 134
#define OUT_SMEM (OUT_SO + 64*SOSTR*4)

__global__ void __launch_bounds__(256, 2) out_kernel(
    const float* __restrict__ Wo, const float* __restrict__ bo,
    const float* __restrict__ feat0, float* __restrict__ out)
{
    extern __shared__ __align__(128) char smc[];
    __half* s_w = reinterpret_cast<__half*>(smc + OUT_SW);
    float*  s_o = reinterpret_cast<float*>(smc + OUT_SO);
    const uint32_t smem_u32 = (uint32_t)__cvta_generic_to_shared(smc);

    const int b  = blockIdx.y;
    const int q0 = blockIdx.x * 64;
    const int tid = threadIdx.x;
    const int lane = tid & 31;
    const int wid  = tid >> 5;
    const int wm   = wid & 3;
    const int wn   = wid >> 2;
    const int l4   = lane & 3;
    const int ld   = lane >> 2;
    const int r0   = 16*wm + ld;
    const int li = lane & 7, lg = lane >> 3;

    #pragma unroll
    for (int j = 0; j < 4; j++) {
        int idx = j*256 + tid;
        int q = idx >> 4, ck = idx & 15;
        CP_ASYNC16(smem_u32 + OUT_SA + (uint32_t)(q*(STRH*2) + ck*16),
                   g_attn + (size_t)(b*WHQ + q0 + q)*CC + ck*8);
    }
    CP_COMMIT();
    // Wo row-major: s_w[c][j]
    #pragma unroll
    for (int i = tid; i < 128*CC; i += 256) {
        int c = i >> 7, j = i & 127;
        s_w[c*STRH + j] = __float2half_rn(Wo[c*CC + j]);
    }
    CP_WAIT0();
    __syncthreads();

    const uint32_t a_off = smem_u32 + OUT_SA +
        (uint32_t)((16*wm + (lg&1)*8 + li)*(STRH*2) + (lg>>1)*16);
    const uint32_t wb_off = smem_u32 + OUT_SW +
        (uint32_t)(((lg&1)*8 + li)*(STRH*2) + ((lg>>1)*8)*2);

    float acc[8][4];
    #pragma unroll
    for (int i = 0; i < 8; i++)
        #pragma unroll
        for (int j = 0; j < 4; j++) acc[i][j] = 0.f;

    #pragma unroll
    for (int kc = 0; kc < 8; kc++) {
        uint32_t a[4];
        LDMX4(a[0], a[1], a[2], a[3], a_off + kc*32);
        #pragma unroll
        for (int nt2 = 0; nt2 < 4; nt2++) {
            const int col0 = 64*wn + 16*nt2;
            uint32_t b0, b1, b2, b3;
            LDMX4T(b0, b1, b2, b3, wb_off + (uint32_t)(kc*16*(STRH*2) + col0*2));
            mma_f16(acc[2*nt2],   a, b0, b1);
            mma_f16(acc[2*nt2+1], a, b2, b3);
        }
    }

    #pragma unroll
    for (int nt = 0; nt < 8; nt++) {
        const int col = 64*wn + 8*nt + 2*l4;
        *reinterpret_cast<float2*>(&s_o[(r0    )*SOSTR + col]) = make_float2(acc[nt][0], acc[nt][1]);
        *reinterpret_cast<float2*>(&s_o[(r0 + 8)*SOSTR + col]) = make_float2(acc[nt][2], acc[nt][3]);
    }
    __syncthreads();

    #pragma unroll
    for (int i = tid; i < 64*CC; i += 256) {
        const int c = i >> 6, q = i & 63;
        const float v = s_o[q*SOSTR + c] + bo[c];
        const float g = __half2float(g_geo[(size_t)(b*WHQ + q0 + q)*CC + c]);
        const float sig = 1.f / (1.f + __expf(-g));
        const size_t oi = (size_t)(b*CC + c)*WHQ + q0 + q;
        out[oi] = v*(1.f + sig) + feat0[oi];
    }
}

// ---------------------------------------------------------------------------
extern "C" void kernel_launch(void* const* d_in, const int* in_sizes, int n_in,
                              void* d_out, int out_size)
{
    const float* feat0     = (const float*)d_in[0];
    const float* feat1     = (const float*)d_in[1];
    const float* geo_embed = (const float*)d_in[2];
    const float* Wq = (const float*)d_in[3];
    const float* bq = (const float*)d_in[4];
    const float* Wk = (const float*)d_in[5];
    const float* bk = (const float*)d_in[6];
    const float* Wv = (const float*)d_in[7];
    const float* bv = (const float*)d_in[8];
    const float* Wo = (const float*)d_in[9];
    const float* bo = (const float*)d_in[10];
    const float* Wg = (const float*)d_in[11];
    const float* bg = (const float*)d_in[12];
    const float* Wgate = (const float*)d_in[13];
    const float* bgate = (const float*)d_in[14];
    float* out = (float*)d_out;

    cudaFuncSetAttribute(attn_kernel,
                         cudaFuncAttributeMaxDynamicSharedMemorySize, ATTN_SMEM_BYTES);
    cudaFuncSetAttribute(kv_proj_kernel,
                         cudaFuncAttributeMaxDynamicSharedMemorySize, KV_SMEM);
    cudaFuncSetAttribute(q_geo_kernel,
                         cudaFuncAttributeMaxDynamicSharedMemorySize, QG_SMEM);
    cudaFuncSetAttribute(out_kernel,
                         cudaFuncAttributeMaxDynamicSharedMemorySize, OUT_SMEM);

    kv_proj_kernel<<<dim3(NN/128, BB), 256, KV_SMEM>>>(feat1, Wk, bk, Wv, bv);
    q_geo_kernel<<<dim3(WHQ/128, BB), 256, QG_SMEM>>>(feat0, geo_embed, Wq, bq, Wg, bg, Wgate, bgate);
    attn_kernel<<<dim3(WHQ/TQ, BB), 256, ATTN_SMEM_BYTES>>>();
    out_kernel<<<dim3(WHQ/64, BB), 256, OUT_SMEM>>>(Wo, bo, feat0, out);
}

// round 17
// speedup vs baseline: 1.0519x; 1.0346x over previous
#include <cuda_runtime.h>
#include <cuda_fp16.h>
#include <cuda_bf16.h>
#include <cstdint>

#define BB   8
#define CC   128
#define WHQ  2304
#define NN   8192

#define TQ   64
#define TN   64
#define NT   (NN/TN)
#define STRH 136     // universal b16 tile stride (halves): 272B rows, ldmatrix conflict-free

// Scratch (device globals: allocation-free rule)
__device__ __half        g_pk  [BB*NN*CC];   // [b, n, c] fp16
__device__ __nv_bfloat16 g_pv  [BB*NN*CC];   // [b, n, c] bf16
__device__ __half        g_pq  [BB*WHQ*CC];  // fp16
__device__ __half        g_geo [BB*WHQ*CC];  // fp16
__device__ __half        g_attn[BB*WHQ*CC];  // fp16

__device__ __forceinline__ void mma_f16(float c[4], const uint32_t a[4], uint32_t b0, uint32_t b1) {
    asm volatile(
        "mma.sync.aligned.m16n8k16.row.col.f32.f16.f16.f32 "
        "{%0,%1,%2,%3}, {%4,%5,%6,%7}, {%8,%9}, {%0,%1,%2,%3};"
        : "+f"(c[0]), "+f"(c[1]), "+f"(c[2]), "+f"(c[3])
        : "r"(a[0]), "r"(a[1]), "r"(a[2]), "r"(a[3]), "r"(b0), "r"(b1));
}

__device__ __forceinline__ void mma_bf16(float c[4], const uint32_t a[4], uint32_t b0, uint32_t b1) {
    asm volatile(
        "mma.sync.aligned.m16n8k16.row.col.f32.bf16.bf16.f32 "
        "{%0,%1,%2,%3}, {%4,%5,%6,%7}, {%8,%9}, {%0,%1,%2,%3};"
        : "+f"(c[0]), "+f"(c[1]), "+f"(c[2]), "+f"(c[3])
        : "r"(a[0]), "r"(a[1]), "r"(a[2]), "r"(a[3]), "r"(b0), "r"(b1));
}

__device__ __forceinline__ uint32_t pack_bf16(float hi, float lo) {
    uint32_t r;
    asm("cvt.rn.bf16x2.f32 %0, %1, %2;" : "=r"(r) : "f"(hi), "f"(lo));
    return r;
}

#define LDMX4(r0, r1, r2, r3, addr) \
    asm volatile("ldmatrix.sync.aligned.m8n8.x4.shared.b16 {%0,%1,%2,%3}, [%4];" \
        : "=r"(r0), "=r"(r1), "=r"(r2), "=r"(r3) : "r"(addr))
#define LDMX4T(r0, r1, r2, r3, addr) \
    asm volatile("ldmatrix.sync.aligned.m8n8.x4.trans.shared.b16 {%0,%1,%2,%3}, [%4];" \
        : "=r"(r0), "=r"(r1), "=r"(r2), "=r"(r3) : "r"(addr))

#define CP_ASYNC16(dst_u32, src_ptr) \
    asm volatile("cp.async.cg.shared.global [%0], [%1], 16;" :: "r"(dst_u32), "l"(src_ptr))
#define CP_COMMIT() asm volatile("cp.async.commit_group;")
#define CP_WAIT0()  asm volatile("cp.async.wait_group 0;" ::: "memory")

// ---------------------------------------------------------------------------
// K1: MERGED projection kernel.
//   blockIdx.x <  64: KV path (128 n-rows)   — pk fp16, pv bf16
//   blockIdx.x >= 64: QG path (64 q-rows)    — pq (gated) fp16, geo fp16
//   Both paths: weights staged row-major (conflict-free), B-frags via LDMX4T.
//   smem: KV 104448 B, QG 104960 B -> 105472 alloc, occupancy 2.
// ---------------------------------------------------------------------------
#define WT_BYTES (128*STRH*2)            // 34816 per weight tile
#define PRJ_SMEM (34816 + 2*WT_BYTES + 1024)

__global__ void __launch_bounds__(256, 2) proj_kernel(
    const float* __restrict__ feat1,
    const float* __restrict__ Wk, const float* __restrict__ bk,
    const float* __restrict__ Wv, const float* __restrict__ bv,
    const float* __restrict__ feat0, const float* __restrict__ geo_embed,
    const float* __restrict__ Wq, const float* __restrict__ bq,
    const float* __restrict__ Wg, const float* __restrict__ bg,
    const float* __restrict__ Wgate, const float* __restrict__ bgate)
{
    extern __shared__ __align__(128) char smc[];
    const uint32_t smem_u32 = (uint32_t)__cvta_generic_to_shared(smc);

    const int b  = blockIdx.y;
    const int tid = threadIdx.x;
    const int lane = tid & 31;
    const int wid  = tid >> 5;
    const int wm   = wid & 3;
    const int wn   = wid >> 2;
    const int l4   = lane & 3;
    const int ld   = lane >> 2;
    const int li   = lane & 7, lg = lane >> 3;

    // trans B-frag lane offset (shared by both paths)
    const uint32_t wb_off = (uint32_t)(((lg&1)*8 + li)*(STRH*2) + ((lg>>1)*8)*2);

    if (blockIdx.x < 64) {
        // ================= KV path =================
        const int n0 = blockIdx.x * 128;
        __half* s_a = reinterpret_cast<__half*>(smc);
        __half* s_w = reinterpret_cast<__half*>(smc + 34816);

        #pragma unroll
        for (int i = tid; i < 128*CC; i += 256) {
            int c = i >> 7, nl = i & 127;
            s_a[nl*STRH + c] = __float2half_rn(feat1[(size_t)(b*CC + c)*NN + n0 + nl]);
        }
        #pragma unroll
        for (int i = tid; i < 2*128*CC; i += 256) {
            int w = i >> 14, rem = i & 16383;
            int c = rem >> 7, j = rem & 127;
            const float* W = w ? Wv : Wk;
            s_w[(w*128 + c)*STRH + j] = __float2half_rn(W[c*CC + j]);
        }
        __syncthreads();

        #pragma unroll
        for (int mb = 0; mb < 2; mb++) {
            const uint32_t a_off = smem_u32 +
                (uint32_t)((32*wm + 16*mb + (lg&1)*8 + li)*(STRH*2) + (lg>>1)*16);
            uint32_t a[8][4];
            #pragma unroll
            for (int kc = 0; kc < 8; kc++)
                LDMX4(a[kc][0], a[kc][1], a[kc][2], a[kc][3], a_off + kc*32);

            float acc[16][4];
            #pragma unroll
            for (int nt2 = 0; nt2 < 8; nt2++) {
                const float* bias = (nt2 < 4) ? bk : bv;
                const int c1 = 64*wn + 16*(nt2 & 3) + 2*l4;
                acc[2*nt2][0] = bias[c1];     acc[2*nt2][1] = bias[c1+1];
                acc[2*nt2][2] = bias[c1];     acc[2*nt2][3] = bias[c1+1];
                acc[2*nt2+1][0] = bias[c1+8]; acc[2*nt2+1][1] = bias[c1+9];
                acc[2*nt2+1][2] = bias[c1+8]; acc[2*nt2+1][3] = bias[c1+9];
            }

            #pragma unroll
            for (int kc = 0; kc < 8; kc++) {
                #pragma unroll
                for (int nt2 = 0; nt2 < 8; nt2++) {
                    const uint32_t tile = smem_u32 + 34816 + ((nt2 >= 4) ? WT_BYTES : 0);
                    const int col0 = 64*wn + 16*(nt2 & 3);
                    uint32_t b0, b1, b2, b3;
                    LDMX4T(b0, b1, b2, b3,
                           tile + wb_off + (uint32_t)(kc*16*(STRH*2) + col0*2));
                    mma_f16(acc[2*nt2],   a[kc], b0, b1);
                    mma_f16(acc[2*nt2+1], a[kc], b2, b3);
                }
            }

            const int nr0 = n0 + 32*wm + 16*mb + ld;
            #pragma unroll
            for (int nt2 = 0; nt2 < 8; nt2++) {
                const int c1 = 64*wn + 16*(nt2 & 3) + 2*l4;
                if (nt2 < 4) {
                    *reinterpret_cast<__half2*>(&g_pk[(size_t)(b*NN + nr0)*CC + c1]) =
                        __floats2half2_rn(acc[2*nt2][0], acc[2*nt2][1]);
                    *reinterpret_cast<__half2*>(&g_pk[(size_t)(b*NN + nr0 + 8)*CC + c1]) =
                        __floats2half2_rn(acc[2*nt2][2], acc[2*nt2][3]);
                    *reinterpret_cast<__half2*>(&g_pk[(size_t)(b*NN + nr0)*CC + c1 + 8]) =
                        __floats2half2_rn(acc[2*nt2+1][0], acc[2*nt2+1][1]);
                    *reinterpret_cast<__half2*>(&g_pk[(size_t)(b*NN + nr0 + 8)*CC + c1 + 8]) =
                        __floats2half2_rn(acc[2*nt2+1][2], acc[2*nt2+1][3]);
                } else {
                    *reinterpret_cast<uint32_t*>(&g_pv[(size_t)(b*NN + nr0)*CC + c1]) =
                        pack_bf16(acc[2*nt2][1], acc[2*nt2][0]);
                    *reinterpret_cast<uint32_t*>(&g_pv[(size_t)(b*NN + nr0 + 8)*CC + c1]) =
                        pack_bf16(acc[2*nt2][3], acc[2*nt2][2]);
                    *reinterpret_cast<uint32_t*>(&g_pv[(size_t)(b*NN + nr0)*CC + c1 + 8]) =
                        pack_bf16(acc[2*nt2+1][1], acc[2*nt2+1][0]);
                    *reinterpret_cast<uint32_t*>(&g_pv[(size_t)(b*NN + nr0 + 8)*CC + c1 + 8]) =
                        pack_bf16(acc[2*nt2+1][3], acc[2*nt2+1][2]);
                }
            }
            if (mb == 0) __syncthreads();
        }
    } else {
        // ================= QG path (64 q-rows) =================
        const int q0 = (blockIdx.x - 64) * 64;
        __half* s_q = reinterpret_cast<__half*>(smc);
        __half* s_g = reinterpret_cast<__half*>(smc + 17408);
        __half* s_w = reinterpret_cast<__half*>(smc + 34816);
        float*  s_red = reinterpret_cast<float*>(smc + 34816 + 2*WT_BYTES);  // 2*64 floats

        #pragma unroll
        for (int i = tid; i < 64*CC; i += 256) {
            int c = i >> 6, ql = i & 63;
            s_q[ql*STRH + c] = __float2half_rn(feat0[(size_t)(b*CC + c)*WHQ + q0 + ql]);
        }
        #pragma unroll
        for (int i = tid; i < 64*CC; i += 256) {
            int ql = i >> 7, c = i & 127;
            s_g[ql*STRH + c] = __float2half_rn(geo_embed[(size_t)(b*WHQ + q0 + ql)*CC + c]);
        }
        #pragma unroll
        for (int i = tid; i < 2*128*CC; i += 256) {
            int w = i >> 14, rem = i & 16383;
            int c = rem >> 7, j = rem & 127;
            const float* W = w ? Wg : Wq;
            s_w[(w*128 + c)*STRH + j] = __float2half_rn(W[c*CC + j]);
        }
        __syncthreads();

        const uint32_t frag_off =
            (uint32_t)((16*wm + (lg&1)*8 + li)*(STRH*2) + (lg>>1)*16);
        const float gbias = bgate[0];

        float acc[16][4];
        #pragma unroll
        for (int nt2 = 0; nt2 < 8; nt2++) {
            const float* bias = (nt2 < 4) ? bq : bg;
            const int c1 = 64*wn + 16*(nt2 & 3) + 2*l4;
            acc[2*nt2][0] = bias[c1];     acc[2*nt2][1] = bias[c1+1];
            acc[2*nt2][2] = bias[c1];     acc[2*nt2][3] = bias[c1+1];
            acc[2*nt2+1][0] = bias[c1+8]; acc[2*nt2+1][1] = bias[c1+9];
            acc[2*nt2+1][2] = bias[c1+8]; acc[2*nt2+1][3] = bias[c1+9];
        }

        #pragma unroll
        for (int kc = 0; kc < 8; kc++) {
            uint32_t aq[4], ag[4];
            LDMX4(aq[0], aq[1], aq[2], aq[3], smem_u32 + frag_off + kc*32);
            LDMX4(ag[0], ag[1], ag[2], ag[3], smem_u32 + 17408 + frag_off + kc*32);
            #pragma unroll
            for (int nt2 = 0; nt2 < 8; nt2++) {
                const uint32_t tile = smem_u32 + 34816 + ((nt2 >= 4) ? WT_BYTES : 0);
                const int col0 = 64*wn + 16*(nt2 & 3);
                uint32_t b0, b1, b2, b3;
                LDMX4T(b0, b1, b2, b3,
                       tile + wb_off + (uint32_t)(kc*16*(STRH*2) + col0*2));
                const uint32_t* A = (nt2 < 4) ? aq : ag;
                mma_f16(acc[2*nt2],   A, b0, b1);
                mma_f16(acc[2*nt2+1], A, b2, b3);
            }
        }

        // gate partials
        float p0 = 0.f, p1 = 0.f;
        #pragma unroll
        for (int nt2 = 0; nt2 < 4; nt2++) {
            const int c1 = 64*wn + 16*nt2 + 2*l4;
            const float wq0 = Wgate[c1], wq1 = Wgate[c1+1], wq8 = Wgate[c1+8], wq9 = Wgate[c1+9];
            const float wg0 = Wgate[CC+c1], wg1 = Wgate[CC+c1+1], wg8 = Wgate[CC+c1+8], wg9 = Wgate[CC+c1+9];
            p0 += acc[2*nt2][0]*wq0 + acc[2*nt2][1]*wq1 + acc[2*nt2+1][0]*wq8 + acc[2*nt2+1][1]*wq9
                + acc[8+2*nt2][0]*wg0 + acc[8+2*nt2][1]*wg1 + acc[9+2*nt2][0]*wg8 + acc[9+2*nt2][1]*wg9;
            p1 += acc[2*nt2][2]*wq0 + acc[2*nt2][3]*wq1 + acc[2*nt2+1][2]*wq8 + acc[2*nt2+1][3]*wq9
                + acc[8+2*nt2][2]*wg0 + acc[8+2*nt2][3]*wg1 + acc[9+2*nt2][2]*wg8 + acc[9+2*nt2][3]*wg9;
        }
        p0 += __shfl_xor_sync(0xffffffffu, p0, 1);
        p0 += __shfl_xor_sync(0xffffffffu, p0, 2);
        p1 += __shfl_xor_sync(0xffffffffu, p1, 1);
        p1 += __shfl_xor_sync(0xffffffffu, p1, 2);
        const int lr0 = 16*wm + ld;
        if (l4 == 0) { s_red[wn*64 + lr0] = p0; s_red[wn*64 + lr0 + 8] = p1; }
        __syncthreads();

        const float gate0 = 1.f / (1.f + __expf(-(s_red[lr0]     + s_red[64 + lr0]     + gbias)));
        const float gate1 = 1.f / (1.f + __expf(-(s_red[lr0 + 8] + s_red[64 + lr0 + 8] + gbias)));

        const size_t row0 = (size_t)(b*WHQ + q0 + lr0)*CC;
        const size_t row1 = (size_t)(b*WHQ + q0 + lr0 + 8)*CC;
        #pragma unroll
        for (int nt2 = 0; nt2 < 4; nt2++) {
            const int c1 = 64*wn + 16*nt2 + 2*l4;
            *reinterpret_cast<__half2*>(&g_pq[row0 + c1]) =
                __floats2half2_rn(acc[2*nt2][0] + gate0*acc[8+2*nt2][0],
                                  acc[2*nt2][1] + gate0*acc[8+2*nt2][1]);
            *reinterpret_cast<__half2*>(&g_pq[row1 + c1]) =
                __floats2half2_rn(acc[2*nt2][2] + gate1*acc[8+2*nt2][2],
                                  acc[2*nt2][3] + gate1*acc[8+2*nt2][3]);
            *reinterpret_cast<__half2*>(&g_pq[row0 + c1 + 8]) =
                __floats2half2_rn(acc[2*nt2+1][0] + gate0*acc[9+2*nt2][0],
                                  acc[2*nt2+1][1] + gate0*acc[9+2*nt2][1]);
            *reinterpret_cast<__half2*>(&g_pq[row1 + c1 + 8]) =
                __floats2half2_rn(acc[2*nt2+1][2] + gate1*acc[9+2*nt2][2],
                                  acc[2*nt2+1][3] + gate1*acc[9+2*nt2][3]);

            *reinterpret_cast<__half2*>(&g_geo[row0 + c1]) =
                __floats2half2_rn(acc[8+2*nt2][0], acc[8+2*nt2][1]);
            *reinterpret_cast<__half2*>(&g_geo[row1 + c1]) =
                __floats2half2_rn(acc[8+2*nt2][2], acc[8+2*nt2][3]);
            *reinterpret_cast<__half2*>(&g_geo[row0 + c1 + 8]) =
                __floats2half2_rn(acc[9+2*nt2][0], acc[9+2*nt2][1]);
            *reinterpret_cast<__half2*>(&g_geo[row1 + c1 + 8]) =
                __floats2half2_rn(acc[9+2*nt2][2], acc[9+2*nt2][3]);
        }
    }
}

// ---------------------------------------------------------------------------
// K3: flash attention, occupancy 2 (unchanged)
// ---------------------------------------------------------------------------
#define SM_QB  0
#define SM_K0B (TQ*STRH*2)
#define SM_K1B (2*TQ*STRH*2)
#define SM_V0B (3*TQ*STRH*2)
#define SM_V1B (4*TQ*STRH*2)
#define SM_MXB (5*TQ*STRH*2)
#define SM_LWB (SM_MXB + 512)
#define ATTN_SMEM_BYTES (SM_LWB + 512)

__global__ void __launch_bounds__(256, 2) attn_kernel()
{
    extern __shared__ __align__(128) char smc[];
    float* smf = reinterpret_cast<float*>(smc);
    const uint32_t smem_u32 = (uint32_t)__cvta_generic_to_shared(smc);

    const int b   = blockIdx.y;
    const int q0  = blockIdx.x * TQ;
    const int tid = threadIdx.x;
    const int lane = tid & 31;
    const int wid  = tid >> 5;
    const int wm   = wid & 3;
    const int wn   = wid >> 2;
    const int l4   = lane & 3;
    const int ld   = lane >> 2;
    const int r0   = 16*wm + ld;

    float* s_mx = smf + SM_MXB/4;
    float* s_lw = smf + SM_LWB/4;

    const __half* gq = g_pq + (size_t)(b*WHQ + q0)*CC;
    const __half* gk = g_pk + (size_t)b*NN*CC;
    const __nv_bfloat16* gv = g_pv + (size_t)b*NN*CC;

    const int li = lane & 7, lg = lane >> 3;
    const uint32_t q_off = smem_u32 + SM_QB +
        (uint32_t)((16*wm + (lg&1)*8 + li)*(STRH*2) + (lg>>1)*16);
    const uint32_t k_off = (uint32_t)((32*wn + (lg>>1)*8 + li)*(STRH*2) + (lg&1)*16);
    const uint32_t v_off = (uint32_t)((32*wn + (lg&1)*8 + li)*(STRH*2) + ((lg>>1)*8)*2);

    #pragma unroll
    for (int j = 0; j < 4; j++) {
        int idx = j*256 + tid;
        int n = idx >> 4, ck = idx & 15;
        CP_ASYNC16(smem_u32 + SM_QB + (uint32_t)(n*(STRH*2) + ck*16),
                   gq + (size_t)n*CC + ck*8);
    }
    CP_COMMIT();

    auto load_tile = [&](int t, int buf) {
        const uint32_t kb = smem_u32 + (buf ? SM_K1B : SM_K0B);
        const uint32_t vb = smem_u32 + (buf ? SM_V1B : SM_V0B);
        const __half* ksrc = gk + (size_t)t*TN*CC;
        const __nv_bfloat16* vsrc = gv + (size_t)t*TN*CC;
        #pragma unroll
        for (int j = 0; j < 4; j++) {
            int idx = j*256 + tid;
            int n = idx >> 4, ck = idx & 15;
            CP_ASYNC16(kb + (uint32_t)(n*(STRH*2) + ck*16), ksrc + (size_t)n*CC + ck*8);
            CP_ASYNC16(vb + (uint32_t)(n*(STRH*2) + ck*16), vsrc + (size_t)n*CC + ck*8);
        }
        CP_COMMIT();
    };

    load_tile(0, 0);

    float oacc[16][4];
    #pragma unroll
    for (int i = 0; i < 16; i++)
        #pragma unroll
        for (int j = 0; j < 4; j++) oacc[i][j] = 0.f;
    float l_acc0 = 0.f, l_acc1 = 0.f;
    float m0a = 0.f, m0b = 0.f;

    for (int t = 0; t < NT; ++t) {
        CP_WAIT0();
        __syncthreads();
        if (t + 1 < NT) load_tile(t+1, (t+1)&1);

        const uint32_t kb = smem_u32 + ((t & 1) ? SM_K1B : SM_K0B);
        const uint32_t vb = smem_u32 + ((t & 1) ? SM_V1B : SM_V0B);

        float sacc[4][4];
        #pragma unroll
        for (int nt = 0; nt < 4; nt++)
            #pragma unroll
            for (int j = 0; j < 4; j++) sacc[nt][j] = 0.f;

        #pragma unroll
        for (int kc = 0; kc < 8; kc++) {
            uint32_t qa[4];
            LDMX4(qa[0], qa[1], qa[2], qa[3], q_off + kc*32);
            uint32_t b0, b1, b2, b3, b4, b5, b6, b7;
            LDMX4(b0, b1, b2, b3, kb + k_off + kc*32);
            LDMX4(b4, b5, b6, b7, kb + k_off + 16*(STRH*2) + kc*32);
            mma_f16(sacc[0], qa, b0, b1);
            mma_f16(sacc[1], qa, b2, b3);
            mma_f16(sacc[2], qa, b4, b5);
            mma_f16(sacc[3], qa, b6, b7);
        }

        if (t == 0) {
            float mx0 = -1e30f, mx1 = -1e30f;
            #pragma unroll
            for (int nt = 0; nt < 4; nt++) {
                mx0 = fmaxf(mx0, fmaxf(sacc[nt][0], sacc[nt][1]));
                mx1 = fmaxf(mx1, fmaxf(sacc[nt][2], sacc[nt][3]));
            }
            mx0 = fmaxf(mx0, __shfl_xor_sync(0xffffffffu, mx0, 1));
            mx0 = fmaxf(mx0, __shfl_xor_sync(0xffffffffu, mx0, 2));
            mx1 = fmaxf(mx1, __shfl_xor_sync(0xffffffffu, mx1, 1));
            mx1 = fmaxf(mx1, __shfl_xor_sync(0xffffffffu, mx1, 2));
            if (l4 == 0) { s_mx[wn*64 + r0] = mx0; s_mx[wn*64 + r0 + 8] = mx1; }
            __syncthreads();
            m0a = fmaxf(s_mx[r0],     s_mx[64 + r0]);
            m0b = fmaxf(s_mx[r0 + 8], s_mx[64 + r0 + 8]);
        }

        uint32_t pa[2][4];
        #pragma unroll
        for (int nt = 0; nt < 4; nt++) {
            float p0 = __expf(sacc[nt][0] - m0a);
            float p1 = __expf(sacc[nt][1] - m0a);
            float p2 = __expf(sacc[nt][2] - m0b);
            float p3 = __expf(sacc[nt][3] - m0b);
            l_acc0 += p0 + p1;
            l_acc1 += p2 + p3;
            const int kc = nt >> 1, o = (nt & 1) ? 2 : 0;
            pa[kc][o + 0] = pack_bf16(p1, p0);
            pa[kc][o + 1] = pack_bf16(p3, p2);
        }

        #pragma unroll
        for (int kc = 0; kc < 2; kc++) {
            const uint32_t vk = vb + v_off + (uint32_t)(kc*16*(STRH*2));
            #pragma unroll
            for (int j = 0; j < 8; j++) {
                uint32_t v0, v1, v2, v3;
                LDMX4T(v0, v1, v2, v3, vk + j*32);
                mma_bf16(oacc[2*j],   pa[kc], v0, v1);
                mma_bf16(oacc[2*j+1], pa[kc], v2, v3);
            }
        }
    }

    l_acc0 += __shfl_xor_sync(0xffffffffu, l_acc0, 1);
    l_acc0 += __shfl_xor_sync(0xffffffffu, l_acc0, 2);
    l_acc1 += __shfl_xor_sync(0xffffffffu, l_acc1, 1);
    l_acc1 += __shfl_xor_sync(0xffffffffu, l_acc1, 2);
    if (l4 == 0) { s_lw[wn*64 + r0] = l_acc0; s_lw[wn*64 + r0 + 8] = l_acc1; }

    float* sO = smf + SM_K0B/4;
    if (wn == 1) {
        #pragma unroll
        for (int nt = 0; nt < 16; nt++) {
            const int col = 8*nt + 2*l4;
            *reinterpret_cast<float2*>(&sO[(r0    )*130 + col]) = make_float2(oacc[nt][0], oacc[nt][1]);
            *reinterpret_cast<float2*>(&sO[(r0 + 8)*130 + col]) = make_float2(oacc[nt][2], oacc[nt][3]);
        }
    }
    __syncthreads();
    if (wn == 0) {
        const float inv0 = 1.f / ((s_lw[r0]     + s_lw[64 + r0]    ) * 11.313708499f);
        const float inv1 = 1.f / ((s_lw[r0 + 8] + s_lw[64 + r0 + 8]) * 11.313708499f);
        #pragma unroll
        for (int nt = 0; nt < 16; nt++) {
            const int col = 8*nt + 2*l4;
            float2 p0 = *reinterpret_cast<const float2*>(&sO[(r0    )*130 + col]);
            float2 p1 = *reinterpret_cast<const float2*>(&sO[(r0 + 8)*130 + col]);
            *reinterpret_cast<__half2*>(&g_attn[(size_t)(b*WHQ + q0 + r0)*CC + col]) =
                __floats2half2_rn((oacc[nt][0] + p0.x)*inv0, (oacc[nt][1] + p0.y)*inv0);
            *reinterpret_cast<__half2*>(&g_attn[(size_t)(b*WHQ + q0 + r0 + 8)*CC + col]) =
                __floats2half2_rn((oacc[nt][2] + p1.x)*inv1, (oacc[nt][3] + p1.y)*inv1);
        }
    }
}

// ---------------------------------------------------------------------------
// K4: tensor-core out projection, 64 q-rows per CTA, occupancy 2. (unchanged)
// ---------------------------------------------------------------------------
#define OUT_SA 0
#define OUT_SW 17408
#define OUT_SO (17408 + 34816)
#define SOSTR 134
#define OUT_SMEM (OUT_SO + 64*SOSTR*4)

__global__ void __launch_bounds__(256, 2) out_kernel(
    const float* __restrict__ Wo, const float* __restrict__ bo,
    const float* __restrict__ feat0, float* __restrict__ out)
{
    extern __shared__ __align__(128) char smc[];
    __half* s_w = reinterpret_cast<__half*>(smc + OUT_SW);
    float*  s_o = reinterpret_cast<float*>(smc + OUT_SO);
    const uint32_t smem_u32 = (uint32_t)__cvta_generic_to_shared(smc);

    const int b  = blockIdx.y;
    const int q0 = blockIdx.x * 64;
    const int tid = threadIdx.x;
    const int lane = tid & 31;
    const int wid  = tid >> 5;
    const int wm   = wid & 3;
    const int wn   = wid >> 2;
    const int l4   = lane & 3;
    const int ld   = lane >> 2;
    const int r0   = 16*wm + ld;
    const int li = lane & 7, lg = lane >> 3;

    #pragma unroll
    for (int j = 0; j < 4; j++) {
        int idx = j*256 + tid;
        int q = idx >> 4, ck = idx & 15;
        CP_ASYNC16(smem_u32 + OUT_SA + (uint32_t)(q*(STRH*2) + ck*16),
                   g_attn + (size_t)(b*WHQ + q0 + q)*CC + ck*8);
    }
    CP_COMMIT();
    #pragma unroll
    for (int i = tid; i < 128*CC; i += 256) {
        int c = i >> 7, j = i & 127;
        s_w[c*STRH + j] = __float2half_rn(Wo[c*CC + j]);
    }
    CP_WAIT0();
    __syncthreads();

    const uint32_t a_off = smem_u32 + OUT_SA +
        (uint32_t)((16*wm + (lg&1)*8 + li)*(STRH*2) + (lg>>1)*16);
    const uint32_t wb_off = smem_u32 + OUT_SW +
        (uint32_t)(((lg&1)*8 + li)*(STRH*2) + ((lg>>1)*8)*2);

    float acc[8][4];
    #pragma unroll
    for (int i = 0; i < 8; i++)
        #pragma unroll
        for (int j = 0; j < 4; j++) acc[i][j] = 0.f;

    #pragma unroll
    for (int kc = 0; kc < 8; kc++) {
        uint32_t a[4];
        LDMX4(a[0], a[1], a[2], a[3], a_off + kc*32);
        #pragma unroll
        for (int nt2 = 0; nt2 < 4; nt2++) {
            const int col0 = 64*wn + 16*nt2;
            uint32_t b0, b1, b2, b3;
            LDMX4T(b0, b1, b2, b3, wb_off + (uint32_t)(kc*16*(STRH*2) + col0*2));
            mma_f16(acc[2*nt2],   a, b0, b1);
            mma_f16(acc[2*nt2+1], a, b2, b3);
        }
    }

    #pragma unroll
    for (int nt = 0; nt < 8; nt++) {
        const int col = 64*wn + 8*nt + 2*l4;
        *reinterpret_cast<float2*>(&s_o[(r0    )*SOSTR + col]) = make_float2(acc[nt][0], acc[nt][1]);
        *reinterpret_cast<float2*>(&s_o[(r0 + 8)*SOSTR + col]) = make_float2(acc[nt][2], acc[nt][3]);
    }
    __syncthreads();

    #pragma unroll
    for (int i = tid; i < 64*CC; i += 256) {
        const int c = i >> 6, q = i & 63;
        const float v = s_o[q*SOSTR + c] + bo[c];
        const float g = __half2float(g_geo[(size_t)(b*WHQ + q0 + q)*CC + c]);
        const float sig = 1.f / (1.f + __expf(-g));
        const size_t oi = (size_t)(b*CC + c)*WHQ + q0 + q;
        out[oi] = v*(1.f + sig) + feat0[oi];
    }
}

// ---------------------------------------------------------------------------
extern "C" void kernel_launch(void* const* d_in, const int* in_sizes, int n_in,
                              void* d_out, int out_size)
{
    const float* feat0     = (const float*)d_in[0];
    const float* feat1     = (const float*)d_in[1];
    const float* geo_embed = (const float*)d_in[2];
    const float* Wq = (const float*)d_in[3];
    const float* bq = (const float*)d_in[4];
    const float* Wk = (const float*)d_in[5];
    const float* bk = (const float*)d_in[6];
    const float* Wv = (const float*)d_in[7];
    const float* bv = (const float*)d_in[8];
    const float* Wo = (const float*)d_in[9];
    const float* bo = (const float*)d_in[10];
    const float* Wg = (const float*)d_in[11];
    const float* bg = (const float*)d_in[12];
    const float* Wgate = (const float*)d_in[13];
    const float* bgate = (const float*)d_in[14];
    float* out = (float*)d_out;

    cudaFuncSetAttribute(attn_kernel,
                         cudaFuncAttributeMaxDynamicSharedMemorySize, ATTN_SMEM_BYTES);
    cudaFuncSetAttribute(proj_kernel,
                         cudaFuncAttributeMaxDynamicSharedMemorySize, PRJ_SMEM);
    cudaFuncSetAttribute(out_kernel,
                         cudaFuncAttributeMaxDynamicSharedMemorySize, OUT_SMEM);

    proj_kernel<<<dim3(64 + WHQ/64, BB), 256, PRJ_SMEM>>>(
        feat1, Wk, bk, Wv, bv, feat0, geo_embed, Wq, bq, Wg, bg, Wgate, bgate);
    attn_kernel<<<dim3(WHQ/TQ, BB), 256, ATTN_SMEM_BYTES>>>();
    out_kernel<<<dim3(WHQ/64, BB), 256, OUT_SMEM>>>(Wo, bo, feat0, out);
}